// round 5
// baseline (speedup 1.0000x reference)
#include <cuda_runtime.h>

// Problem constants
#define BB 8
#define SS 1024
#define CC 512
#define HH 8
#define DH 64
#define MTOT (BB * SS)   // 8192

// Scratch (no cudaMalloc allowed) — 16 MB each
__device__ float g_q[BB * SS * CC];
__device__ float g_k[BB * SS * CC];
__device__ float g_v[BB * SS * CC];
__device__ float g_ctx[BB * SS * CC];

// ---------------------------------------------------------------------------
// GEMM: Y[m,n] = sum_k X[m,k] * W[n,k] + bias[n] (+ skip[m,n])
// X: [M,K] row-major, W: [N,K] row-major (torch Linear convention)
// Block: 64x64 tile, 16x16 threads, 4x4 per thread, BK=16.
// Smem stored k-major with stride 68 so inner loop does float4 reads:
//   Xs[kk][ty*4..] broadcast within a row-group, Ws[kk][tx*4..] spread.
// ---------------------------------------------------------------------------
__global__ __launch_bounds__(256) void gemm_bias_kernel(
    const float* __restrict__ X, const float* __restrict__ W,
    const float* __restrict__ bias, const float* __restrict__ skip,
    float* __restrict__ Y, int M, int N, int K)
{
    __shared__ float Xs[16][68];
    __shared__ float Ws[16][68];

    const int tx = threadIdx.x;          // 0..15 -> output cols
    const int ty = threadIdx.y;          // 0..15 -> output rows
    const int tid = ty * 16 + tx;
    const int m0 = blockIdx.y * 64;
    const int n0 = blockIdx.x * 64;

    float acc[4][4] = {};

    for (int k0 = 0; k0 < K; k0 += 16) {
        // Load 64x16 tiles of X and W, transposed to k-major in smem.
        #pragma unroll
        for (int i = tid; i < 64 * 16; i += 256) {
            int r = i >> 4;
            int c = i & 15;
            Xs[c][r] = X[(size_t)(m0 + r) * K + k0 + c];
            Ws[c][r] = W[(size_t)(n0 + r) * K + k0 + c];
        }
        __syncthreads();

        #pragma unroll
        for (int kk = 0; kk < 16; kk++) {
            float4 a4 = *(const float4*)&Xs[kk][ty * 4];
            float4 b4 = *(const float4*)&Ws[kk][tx * 4];
            float av[4] = {a4.x, a4.y, a4.z, a4.w};
            float bv[4] = {b4.x, b4.y, b4.z, b4.w};
            #pragma unroll
            for (int i = 0; i < 4; i++)
                #pragma unroll
                for (int j = 0; j < 4; j++)
                    acc[i][j] = fmaf(av[i], bv[j], acc[i][j]);
        }
        __syncthreads();
    }

    #pragma unroll
    for (int i = 0; i < 4; i++) {
        int m = m0 + ty * 4 + i;
        #pragma unroll
        for (int j = 0; j < 4; j++) {
            int n = n0 + tx * 4 + j;
            float val = acc[i][j] + bias[n];
            if (skip) val += skip[(size_t)m * N + n];
            Y[(size_t)m * N + n] = val;
        }
    }
}

// ---------------------------------------------------------------------------
// Flash-style attention: one block per (b, h, 64-query tile).
// Online softmax; K/V tiles of 64 keys in smem; P staged through the K buffer.
// q/k/v/ctx layout: [B, S, C] with head h occupying columns h*DH..h*DH+63.
// ---------------------------------------------------------------------------
__global__ __launch_bounds__(256) void attn_kernel(
    const float* __restrict__ q, const float* __restrict__ k,
    const float* __restrict__ v, float* __restrict__ ctx)
{
    extern __shared__ float sm[];
    float* Qs = sm;                 // [64 d][68]: Qs[d*68 + r]   (pre-scaled)
    float* Ks = sm + 64 * 68;       // [64 d][68]: Ks[d*68 + c]; reused as Ps[r*68 + c]
    float* Vs = sm + 2 * 64 * 68;   // [64 key][68]: Vs[c*68 + d]

    const int tx = threadIdx.x;     // key / output-dim tiles
    const int ty = threadIdx.y;     // query rows
    const int tid = ty * 16 + tx;

    const int bh = blockIdx.y;
    const int b = bh >> 3;
    const int h = bh & 7;
    const int q0 = blockIdx.x * 64;
    const float scale = 0.125f;     // 1/sqrt(64)
    const size_t base = (size_t)b * SS * CC + (size_t)h * DH;

    // Load and pre-scale Q tile
    for (int i = tid; i < 64 * 64; i += 256) {
        int r = i >> 6;
        int d = i & 63;
        Qs[d * 68 + r] = q[base + (size_t)(q0 + r) * CC + d] * scale;
    }

    float m_i[4], l_i[4], o[4][4];
    #pragma unroll
    for (int i = 0; i < 4; i++) {
        m_i[i] = -1e30f;
        l_i[i] = 0.0f;
        #pragma unroll
        for (int j = 0; j < 4; j++) o[i][j] = 0.0f;
    }

    for (int kt = 0; kt < SS; kt += 64) {
        __syncthreads();   // smem from previous iter fully consumed; Q visible
        for (int i = tid; i < 64 * 64; i += 256) {
            int r = i >> 6;
            int d = i & 63;
            size_t g = base + (size_t)(kt + r) * CC + d;
            Ks[d * 68 + r] = k[g];
            Vs[r * 68 + d] = v[g];
        }
        __syncthreads();

        // S tile = (Q*scale) @ K^T : rows ty*4+i, key-cols tx*4+j
        float sc[4][4] = {};
        #pragma unroll
        for (int d = 0; d < 64; d++) {
            float4 a4 = *(const float4*)&Qs[d * 68 + ty * 4];
            float4 b4 = *(const float4*)&Ks[d * 68 + tx * 4];
            float av[4] = {a4.x, a4.y, a4.z, a4.w};
            float bv[4] = {b4.x, b4.y, b4.z, b4.w};
            #pragma unroll
            for (int i = 0; i < 4; i++)
                #pragma unroll
                for (int j = 0; j < 4; j++)
                    sc[i][j] = fmaf(av[i], bv[j], sc[i][j]);
        }

        // Online softmax update (reductions across the 16-lane tx group)
        #pragma unroll
        for (int i = 0; i < 4; i++) {
            float mx = fmaxf(fmaxf(sc[i][0], sc[i][1]), fmaxf(sc[i][2], sc[i][3]));
            #pragma unroll
            for (int off = 8; off >= 1; off >>= 1)
                mx = fmaxf(mx, __shfl_xor_sync(0xffffffffu, mx, off));
            float mn = fmaxf(m_i[i], mx);
            float alpha = __expf(m_i[i] - mn);
            m_i[i] = mn;
            float rs = 0.0f;
            #pragma unroll
            for (int j = 0; j < 4; j++) {
                sc[i][j] = __expf(sc[i][j] - mn);
                rs += sc[i][j];
            }
            #pragma unroll
            for (int off = 8; off >= 1; off >>= 1)
                rs += __shfl_xor_sync(0xffffffffu, rs, off);
            l_i[i] = l_i[i] * alpha + rs;
            #pragma unroll
            for (int j = 0; j < 4; j++) o[i][j] *= alpha;
        }

        // Stage P into the K buffer (done reading Ks)
        __syncthreads();
        #pragma unroll
        for (int i = 0; i < 4; i++) {
            float4 p4 = make_float4(sc[i][0], sc[i][1], sc[i][2], sc[i][3]);
            *(float4*)&Ks[(ty * 4 + i) * 68 + tx * 4] = p4;
        }
        __syncthreads();

        // O += P @ V : rows ty*4+i, dims tx*4+j
        #pragma unroll
        for (int kk = 0; kk < 64; kk++) {
            float4 v4 = *(const float4*)&Vs[kk * 68 + tx * 4];
            #pragma unroll
            for (int i = 0; i < 4; i++) {
                float pr = Ks[(ty * 4 + i) * 68 + kk];
                o[i][0] = fmaf(pr, v4.x, o[i][0]);
                o[i][1] = fmaf(pr, v4.y, o[i][1]);
                o[i][2] = fmaf(pr, v4.z, o[i][2]);
                o[i][3] = fmaf(pr, v4.w, o[i][3]);
            }
        }
    }

    // Normalize and write ctx
    #pragma unroll
    for (int i = 0; i < 4; i++) {
        float inv = 1.0f / l_i[i];
        int r = q0 + ty * 4 + i;
        float4 res = make_float4(o[i][0] * inv, o[i][1] * inv,
                                 o[i][2] * inv, o[i][3] * inv);
        *(float4*)&ctx[base + (size_t)r * CC + tx * 4] = res;
    }
}

// ---------------------------------------------------------------------------
// kernel_launch
// Inputs (metadata order): x, skip, Wq, bq, Wk, bk, Wv, bv, Wo, bo
// ---------------------------------------------------------------------------
extern "C" void kernel_launch(void* const* d_in, const int* in_sizes, int n_in,
                              void* d_out, int out_size)
{
    const float* x    = (const float*)d_in[0];
    const float* skip = (const float*)d_in[1];
    const float* Wq   = (const float*)d_in[2];
    const float* bq   = (const float*)d_in[3];
    const float* Wk   = (const float*)d_in[4];
    const float* bk   = (const float*)d_in[5];
    const float* Wv   = (const float*)d_in[6];
    const float* bv   = (const float*)d_in[7];
    const float* Wo   = (const float*)d_in[8];
    const float* bo   = (const float*)d_in[9];
    float* out = (float*)d_out;

    float *qp, *kp, *vp, *cp;
    cudaGetSymbolAddress((void**)&qp, g_q);
    cudaGetSymbolAddress((void**)&kp, g_k);
    cudaGetSymbolAddress((void**)&vp, g_v);
    cudaGetSymbolAddress((void**)&cp, g_ctx);

    const int attn_smem = 3 * 64 * 68 * (int)sizeof(float);  // 52224 B
    cudaFuncSetAttribute(attn_kernel,
                         cudaFuncAttributeMaxDynamicSharedMemorySize, attn_smem);

    dim3 gblk(16, 16);
    dim3 ggrid(CC / 64, MTOT / 64);   // (8, 128)

    // QKV projections
    gemm_bias_kernel<<<ggrid, gblk>>>(x, Wq, bq, nullptr, qp, MTOT, CC, CC);
    gemm_bias_kernel<<<ggrid, gblk>>>(x, Wk, bk, nullptr, kp, MTOT, CC, CC);
    gemm_bias_kernel<<<ggrid, gblk>>>(x, Wv, bv, nullptr, vp, MTOT, CC, CC);

    // Attention
    dim3 agrid(SS / 64, BB * HH);     // (16, 64)
    attn_kernel<<<agrid, gblk, attn_smem>>>(qp, kp, vp, cp);

    // Output projection + skip
    gemm_bias_kernel<<<ggrid, gblk>>>(cp, Wo, bo, skip, out, MTOT, CC, CC);
}

// round 11
// speedup vs baseline: 1.6570x; 1.6570x over previous
#include <cuda_runtime.h>
#include <cuda_bf16.h>

// Problem constants
#define BB 8
#define SS 1024
#define CC 512
#define HH 8
#define DH 64
#define MTOT (BB * SS)   // 8192

// ---------------------------------------------------------------------------
// Scratch (no cudaMalloc allowed)
// ---------------------------------------------------------------------------
__device__ float g_q[MTOT * CC];
__device__ float g_k[MTOT * CC];
__device__ float g_v[MTOT * CC];
__device__ float g_ctx[MTOT * CC];
__device__ __nv_bfloat16 g_xh[MTOT * CC];
__device__ __nv_bfloat16 g_xl[MTOT * CC];
__device__ __nv_bfloat16 g_ch[MTOT * CC];
__device__ __nv_bfloat16 g_cl[MTOT * CC];
__device__ __nv_bfloat16 g_wh[4 * CC * CC];
__device__ __nv_bfloat16 g_wl[4 * CC * CC];

// ---------------------------------------------------------------------------
// PTX helpers (sm_80+ only — NO tcgen05; this bench's ptxas targets sm_103)
// ---------------------------------------------------------------------------
__device__ __forceinline__ unsigned smem_to_u32(const void* p) {
    unsigned a;
    asm("{ .reg .u64 t; cvta.to.shared.u64 t, %1; cvt.u32.u64 %0, t; }"
        : "=r"(a) : "l"(p));
    return a;
}

#define LDMATRIX_X4(r, addr) \
    asm volatile("ldmatrix.sync.aligned.m8n8.x4.shared.b16 {%0,%1,%2,%3}, [%4];" \
        : "=r"((r)[0]), "=r"((r)[1]), "=r"((r)[2]), "=r"((r)[3]) : "r"(addr))

__device__ __forceinline__ void mma_bf16(float* d, const unsigned* a, const unsigned* b) {
    asm volatile(
        "mma.sync.aligned.m16n8k16.row.col.f32.bf16.bf16.f32 "
        "{%0,%1,%2,%3}, {%4,%5,%6,%7}, {%8,%9}, {%0,%1,%2,%3};"
        : "+f"(d[0]), "+f"(d[1]), "+f"(d[2]), "+f"(d[3])
        : "r"(a[0]), "r"(a[1]), "r"(a[2]), "r"(a[3]), "r"(b[0]), "r"(b[1]));
}

// ---------------------------------------------------------------------------
// fp32 -> (bf16 hi, bf16 lo) split. 4 elements per thread.
// ---------------------------------------------------------------------------
__global__ __launch_bounds__(256) void split_kernel(
    const float* __restrict__ src,
    __nv_bfloat16* __restrict__ hi, __nv_bfloat16* __restrict__ lo, int n4)
{
    int i = blockIdx.x * blockDim.x + threadIdx.x;
    if (i >= n4) return;
    float4 v = ((const float4*)src)[i];
    __nv_bfloat16 h0 = __float2bfloat16(v.x);
    __nv_bfloat16 h1 = __float2bfloat16(v.y);
    __nv_bfloat16 h2 = __float2bfloat16(v.z);
    __nv_bfloat16 h3 = __float2bfloat16(v.w);
    __nv_bfloat16 l0 = __float2bfloat16(v.x - __bfloat162float(h0));
    __nv_bfloat16 l1 = __float2bfloat16(v.y - __bfloat162float(h1));
    __nv_bfloat16 l2 = __float2bfloat16(v.z - __bfloat162float(h2));
    __nv_bfloat16 l3 = __float2bfloat16(v.w - __bfloat162float(h3));
    ushort4 hs = make_ushort4(__bfloat16_as_ushort(h0), __bfloat16_as_ushort(h1),
                              __bfloat16_as_ushort(h2), __bfloat16_as_ushort(h3));
    ushort4 ls = make_ushort4(__bfloat16_as_ushort(l0), __bfloat16_as_ushort(l1),
                              __bfloat16_as_ushort(l2), __bfloat16_as_ushort(l3));
    ((ushort4*)hi)[i] = hs;
    ((ushort4*)lo)[i] = ls;
}

// ---------------------------------------------------------------------------
// HMMA GEMM with 2-term bf16 split: Y[m,n] = sum_k X[m,k]*W[n,k] + bias[n]
// (+ skip). CTA tile 128x128, 8 warps as 2(M)x4(N) -> warp tile 64x32.
// K-chunks of 64 bf16; smem row stride 144 B (conflict-free ldmatrix).
// ---------------------------------------------------------------------------
#define KC 64
#define NCHUNK (CC / KC)          // 8
#define SROW 144                  // bytes per smem row (64 bf16 + 8 pad)
#define TILE_B (128 * SROW)       // 18432
#define OFF_AH 0
#define OFF_AL TILE_B
#define OFF_BH (2 * TILE_B)
#define OFF_BL (3 * TILE_B)
#define GEMM_SMEM (4 * TILE_B)    // 73728 B

__global__ __launch_bounds__(256, 2) void gemm_mma(
    const __nv_bfloat16* __restrict__ Ah, const __nv_bfloat16* __restrict__ Al,
    const __nv_bfloat16* __restrict__ Bh, const __nv_bfloat16* __restrict__ Bl,
    const float* __restrict__ bias, const float* __restrict__ skip,
    float* __restrict__ Y)
{
    extern __shared__ char smem[];
    const unsigned sb = smem_to_u32(smem);
    const int tid = threadIdx.x;
    const int wid = tid >> 5;
    const int lane = tid & 31;
    const int m0 = blockIdx.y * 128;
    const int n0 = blockIdx.x * 128;
    const int wm = (wid >> 2) * 64;   // warp M offset: 0 / 64
    const int wn = (wid & 3) * 32;    // warp N offset: 0/32/64/96

    float acc[4][4][4];
    #pragma unroll
    for (int i = 0; i < 4; i++)
        #pragma unroll
        for (int j = 0; j < 4; j++)
            #pragma unroll
            for (int r = 0; r < 4; r++) acc[i][j][r] = 0.0f;

    // ldmatrix lane-address components (constant across chunks)
    const int a_row = (lane & 15);
    const unsigned a_cb = (unsigned)((lane >> 4) * 16);
    const int b_row = (lane & 7) + ((lane >> 4) << 3);
    const unsigned b_cb = (unsigned)(((lane >> 3) & 1) * 16);

    for (int ck = 0; ck < NCHUNK; ck++) {
        // Load 4 tiles of [128 rows x 64 bf16] (16B sectors).
        #pragma unroll
        for (int i = tid; i < 1024; i += 256) {
            int r = i >> 3;
            int sg = i & 7;
            unsigned so = (unsigned)(r * SROW + sg * 16);
            size_t ga = (size_t)(m0 + r) * CC + ck * KC + sg * 8;
            size_t gb = (size_t)(n0 + r) * CC + ck * KC + sg * 8;
            *(uint4*)(smem + OFF_AH + so) = *(const uint4*)(Ah + ga);
            *(uint4*)(smem + OFF_AL + so) = *(const uint4*)(Al + ga);
            *(uint4*)(smem + OFF_BH + so) = *(const uint4*)(Bh + gb);
            *(uint4*)(smem + OFF_BL + so) = *(const uint4*)(Bl + gb);
        }
        __syncthreads();

        #pragma unroll
        for (int ks = 0; ks < KC / 16; ks++) {
            const unsigned kb = (unsigned)(ks * 32);

            // B fragments: 2 x4 loads cover 4 n-tiles (hi & lo)
            unsigned b_hi[2][4], b_lo[2][4];
            #pragma unroll
            for (int bj = 0; bj < 2; bj++) {
                unsigned addr = sb + OFF_BH +
                    (unsigned)((wn + bj * 16 + b_row) * SROW) + kb + b_cb;
                LDMATRIX_X4(b_hi[bj], addr);
                LDMATRIX_X4(b_lo[bj], addr + (OFF_BL - OFF_BH));
            }

            #pragma unroll
            for (int mi = 0; mi < 4; mi++) {
                unsigned a_hi[4], a_lo[4];
                unsigned addr = sb + OFF_AH +
                    (unsigned)((wm + mi * 16 + a_row) * SROW) + kb + a_cb;
                LDMATRIX_X4(a_hi, addr);
                LDMATRIX_X4(a_lo, addr + (OFF_AL - OFF_AH));
                #pragma unroll
                for (int nj = 0; nj < 4; nj++) {
                    const unsigned* bh = &b_hi[nj >> 1][(nj & 1) * 2];
                    const unsigned* bl = &b_lo[nj >> 1][(nj & 1) * 2];
                    mma_bf16(acc[mi][nj], a_hi, bh);
                    mma_bf16(acc[mi][nj], a_hi, bl);
                    mma_bf16(acc[mi][nj], a_lo, bh);
                }
            }
        }
        __syncthreads();
    }

    // Epilogue: d0,d1 -> row g; d2,d3 -> row g+8; cols tig*2,+1
    const int g = lane >> 2;
    const int tg = lane & 3;
    #pragma unroll
    for (int mi = 0; mi < 4; mi++) {
        const int mr = m0 + wm + mi * 16 + g;
        #pragma unroll
        for (int nj = 0; nj < 4; nj++) {
            const int n = n0 + wn + nj * 8 + tg * 2;
            float2 bv = *(const float2*)(bias + n);
            float2 y0, y1;
            y0.x = acc[mi][nj][0] + bv.x;
            y0.y = acc[mi][nj][1] + bv.y;
            y1.x = acc[mi][nj][2] + bv.x;
            y1.y = acc[mi][nj][3] + bv.y;
            if (skip) {
                float2 s0 = *(const float2*)(skip + (size_t)mr * CC + n);
                float2 s1 = *(const float2*)(skip + (size_t)(mr + 8) * CC + n);
                y0.x += s0.x; y0.y += s0.y;
                y1.x += s1.x; y1.y += s1.y;
            }
            *(float2*)(Y + (size_t)mr * CC + n) = y0;
            *(float2*)(Y + (size_t)(mr + 8) * CC + n) = y1;
        }
    }
}

// ---------------------------------------------------------------------------
// Flash-style attention (fp32, unchanged from the passing R5 kernel).
// ---------------------------------------------------------------------------
__global__ __launch_bounds__(256) void attn_kernel(
    const float* __restrict__ q, const float* __restrict__ k,
    const float* __restrict__ v, float* __restrict__ ctx)
{
    extern __shared__ float sm[];
    float* Qs = sm;                 // [64 d][68]
    float* Ks = sm + 64 * 68;       // [64 d][68]; reused as Ps[r*68 + c]
    float* Vs = sm + 2 * 64 * 68;   // [64 key][68]

    const int tx = threadIdx.x;
    const int ty = threadIdx.y;
    const int tid = ty * 16 + tx;

    const int bh = blockIdx.y;
    const int b = bh >> 3;
    const int h = bh & 7;
    const int q0 = blockIdx.x * 64;
    const float scale = 0.125f;
    const size_t base = (size_t)b * SS * CC + (size_t)h * DH;

    for (int i = tid; i < 64 * 64; i += 256) {
        int r = i >> 6;
        int d = i & 63;
        Qs[d * 68 + r] = q[base + (size_t)(q0 + r) * CC + d] * scale;
    }

    float m_i[4], l_i[4], o[4][4];
    #pragma unroll
    for (int i = 0; i < 4; i++) {
        m_i[i] = -1e30f;
        l_i[i] = 0.0f;
        #pragma unroll
        for (int j = 0; j < 4; j++) o[i][j] = 0.0f;
    }

    for (int kt = 0; kt < SS; kt += 64) {
        __syncthreads();
        for (int i = tid; i < 64 * 64; i += 256) {
            int r = i >> 6;
            int d = i & 63;
            size_t gg = base + (size_t)(kt + r) * CC + d;
            Ks[d * 68 + r] = k[gg];
            Vs[r * 68 + d] = v[gg];
        }
        __syncthreads();

        float sc[4][4] = {};
        #pragma unroll
        for (int d = 0; d < 64; d++) {
            float4 a4 = *(const float4*)&Qs[d * 68 + ty * 4];
            float4 b4 = *(const float4*)&Ks[d * 68 + tx * 4];
            float av[4] = {a4.x, a4.y, a4.z, a4.w};
            float bv[4] = {b4.x, b4.y, b4.z, b4.w};
            #pragma unroll
            for (int i = 0; i < 4; i++)
                #pragma unroll
                for (int j = 0; j < 4; j++)
                    sc[i][j] = fmaf(av[i], bv[j], sc[i][j]);
        }

        #pragma unroll
        for (int i = 0; i < 4; i++) {
            float mx = fmaxf(fmaxf(sc[i][0], sc[i][1]), fmaxf(sc[i][2], sc[i][3]));
            #pragma unroll
            for (int off = 8; off >= 1; off >>= 1)
                mx = fmaxf(mx, __shfl_xor_sync(0xffffffffu, mx, off));
            float mn = fmaxf(m_i[i], mx);
            float alpha = __expf(m_i[i] - mn);
            m_i[i] = mn;
            float rs = 0.0f;
            #pragma unroll
            for (int j = 0; j < 4; j++) {
                sc[i][j] = __expf(sc[i][j] - mn);
                rs += sc[i][j];
            }
            #pragma unroll
            for (int off = 8; off >= 1; off >>= 1)
                rs += __shfl_xor_sync(0xffffffffu, rs, off);
            l_i[i] = l_i[i] * alpha + rs;
            #pragma unroll
            for (int j = 0; j < 4; j++) o[i][j] *= alpha;
        }

        __syncthreads();
        #pragma unroll
        for (int i = 0; i < 4; i++) {
            float4 p4 = make_float4(sc[i][0], sc[i][1], sc[i][2], sc[i][3]);
            *(float4*)&Ks[(ty * 4 + i) * 68 + tx * 4] = p4;
        }
        __syncthreads();

        #pragma unroll
        for (int kk = 0; kk < 64; kk++) {
            float4 v4 = *(const float4*)&Vs[kk * 68 + tx * 4];
            #pragma unroll
            for (int i = 0; i < 4; i++) {
                float pr = Ks[(ty * 4 + i) * 68 + kk];
                o[i][0] = fmaf(pr, v4.x, o[i][0]);
                o[i][1] = fmaf(pr, v4.y, o[i][1]);
                o[i][2] = fmaf(pr, v4.z, o[i][2]);
                o[i][3] = fmaf(pr, v4.w, o[i][3]);
            }
        }
    }

    #pragma unroll
    for (int i = 0; i < 4; i++) {
        float inv = 1.0f / l_i[i];
        int r = q0 + ty * 4 + i;
        float4 res = make_float4(o[i][0] * inv, o[i][1] * inv,
                                 o[i][2] * inv, o[i][3] * inv);
        *(float4*)&ctx[base + (size_t)r * CC + tx * 4] = res;
    }
}

// ---------------------------------------------------------------------------
// kernel_launch
// Inputs: x, skip, Wq, bq, Wk, bk, Wv, bv, Wo, bo
// ---------------------------------------------------------------------------
extern "C" void kernel_launch(void* const* d_in, const int* in_sizes, int n_in,
                              void* d_out, int out_size)
{
    const float* x    = (const float*)d_in[0];
    const float* skip = (const float*)d_in[1];
    const float* Wq   = (const float*)d_in[2];
    const float* bq   = (const float*)d_in[3];
    const float* Wk   = (const float*)d_in[4];
    const float* bk   = (const float*)d_in[5];
    const float* Wv   = (const float*)d_in[6];
    const float* bv   = (const float*)d_in[7];
    const float* Wo   = (const float*)d_in[8];
    const float* bo   = (const float*)d_in[9];
    float* out = (float*)d_out;

    float *qp, *kp, *vp, *cp;
    __nv_bfloat16 *xh, *xl, *ch, *cl, *wh, *wl;
    cudaGetSymbolAddress((void**)&qp, g_q);
    cudaGetSymbolAddress((void**)&kp, g_k);
    cudaGetSymbolAddress((void**)&vp, g_v);
    cudaGetSymbolAddress((void**)&cp, g_ctx);
    cudaGetSymbolAddress((void**)&xh, g_xh);
    cudaGetSymbolAddress((void**)&xl, g_xl);
    cudaGetSymbolAddress((void**)&ch, g_ch);
    cudaGetSymbolAddress((void**)&cl, g_cl);
    cudaGetSymbolAddress((void**)&wh, g_wh);
    cudaGetSymbolAddress((void**)&wl, g_wl);

    const int attn_smem = 3 * 64 * 68 * (int)sizeof(float);  // 52224 B
    cudaFuncSetAttribute(attn_kernel,
                         cudaFuncAttributeMaxDynamicSharedMemorySize, attn_smem);
    cudaFuncSetAttribute(gemm_mma,
                         cudaFuncAttributeMaxDynamicSharedMemorySize, GEMM_SMEM);

    // --- splits ---
    const int n4x = MTOT * CC / 4;     // 1048576
    const int n4w = CC * CC / 4;       // 65536
    split_kernel<<<n4x / 256, 256>>>(x, xh, xl, n4x);
    split_kernel<<<n4w / 256, 256>>>(Wq, wh,               wl,               n4w);
    split_kernel<<<n4w / 256, 256>>>(Wk, wh + CC * CC,     wl + CC * CC,     n4w);
    split_kernel<<<n4w / 256, 256>>>(Wv, wh + 2 * CC * CC, wl + 2 * CC * CC, n4w);
    split_kernel<<<n4w / 256, 256>>>(Wo, wh + 3 * CC * CC, wl + 3 * CC * CC, n4w);

    // --- QKV projections (HMMA, bf16-split) ---
    dim3 tg(CC / 128, MTOT / 128);     // (4, 64)
    gemm_mma<<<tg, 256, GEMM_SMEM>>>(xh, xl, wh,               wl,               bq, nullptr, qp);
    gemm_mma<<<tg, 256, GEMM_SMEM>>>(xh, xl, wh + CC * CC,     wl + CC * CC,     bk, nullptr, kp);
    gemm_mma<<<tg, 256, GEMM_SMEM>>>(xh, xl, wh + 2 * CC * CC, wl + 2 * CC * CC, bv, nullptr, vp);

    // --- attention (fp32) ---
    dim3 gblk(16, 16);
    dim3 agrid(SS / 64, BB * HH);      // (16, 64)
    attn_kernel<<<agrid, gblk, attn_smem>>>(qp, kp, vp, cp);

    // --- output projection + skip (HMMA, bf16-split) ---
    split_kernel<<<n4x / 256, 256>>>(cp, ch, cl, n4x);
    gemm_mma<<<tg, 256, GEMM_SMEM>>>(ch, cl, wh + 3 * CC * CC, wl + 3 * CC * CC, bo, skip, out);
}

// round 16
// speedup vs baseline: 2.9123x; 1.7575x over previous
#include <cuda_runtime.h>
#include <cuda_bf16.h>

// Problem constants
#define BB 8
#define SS 1024
#define CC 512
#define HH 8
#define DH 64
#define MTOT (BB * SS)   // 8192

// ---------------------------------------------------------------------------
// Scratch (no cudaMalloc allowed)
// ---------------------------------------------------------------------------
__device__ __nv_bfloat16 g_xh[MTOT * CC];
__device__ __nv_bfloat16 g_xl[MTOT * CC];
__device__ __nv_bfloat16 g_qh[MTOT * CC];
__device__ __nv_bfloat16 g_ql[MTOT * CC];
__device__ __nv_bfloat16 g_kh[MTOT * CC];
__device__ __nv_bfloat16 g_kl[MTOT * CC];
__device__ __nv_bfloat16 g_vh[MTOT * CC];
__device__ __nv_bfloat16 g_vl[MTOT * CC];
__device__ __nv_bfloat16 g_ch[MTOT * CC];
__device__ __nv_bfloat16 g_cl[MTOT * CC];
__device__ __nv_bfloat16 g_wh[4 * CC * CC];
__device__ __nv_bfloat16 g_wl[4 * CC * CC];

// ---------------------------------------------------------------------------
// PTX helpers (sm_80-era only — ptxas here targets plain sm_103, no tcgen05)
// ---------------------------------------------------------------------------
__device__ __forceinline__ unsigned smem_to_u32(const void* p) {
    unsigned a;
    asm("{ .reg .u64 t; cvta.to.shared.u64 t, %1; cvt.u32.u64 %0, t; }"
        : "=r"(a) : "l"(p));
    return a;
}

#define LDMATRIX_X4(r, addr) \
    asm volatile("ldmatrix.sync.aligned.m8n8.x4.shared.b16 {%0,%1,%2,%3}, [%4];" \
        : "=r"((r)[0]), "=r"((r)[1]), "=r"((r)[2]), "=r"((r)[3]) : "r"(addr))

#define LDMATRIX_X4_TRANS(r, addr) \
    asm volatile("ldmatrix.sync.aligned.m8n8.x4.trans.shared.b16 {%0,%1,%2,%3}, [%4];" \
        : "=r"((r)[0]), "=r"((r)[1]), "=r"((r)[2]), "=r"((r)[3]) : "r"(addr))

__device__ __forceinline__ void mma_bf16(float* d, const unsigned* a, const unsigned* b) {
    asm volatile(
        "mma.sync.aligned.m16n8k16.row.col.f32.bf16.bf16.f32 "
        "{%0,%1,%2,%3}, {%4,%5,%6,%7}, {%8,%9}, {%0,%1,%2,%3};"
        : "+f"(d[0]), "+f"(d[1]), "+f"(d[2]), "+f"(d[3])
        : "r"(a[0]), "r"(a[1]), "r"(a[2]), "r"(a[3]), "r"(b[0]), "r"(b[1]));
}

// Split a float pair into packed bf16x2 hi and lo parts (x -> low element).
__device__ __forceinline__ void split2(float x, float y, unsigned& h, unsigned& l) {
    __nv_bfloat162 hb = __floats2bfloat162_rn(x, y);
    float hx = __bfloat162float(__low2bfloat16(hb));
    float hy = __bfloat162float(__high2bfloat16(hb));
    __nv_bfloat162 lb = __floats2bfloat162_rn(x - hx, y - hy);
    h = *(unsigned*)&hb;
    l = *(unsigned*)&lb;
}

// ---------------------------------------------------------------------------
// fp32 -> (bf16 hi, bf16 lo) split. 4 elements per thread.
// ---------------------------------------------------------------------------
__global__ __launch_bounds__(256) void split_kernel(
    const float* __restrict__ src,
    __nv_bfloat16* __restrict__ hi, __nv_bfloat16* __restrict__ lo, int n4)
{
    int i = blockIdx.x * blockDim.x + threadIdx.x;
    if (i >= n4) return;
    float4 v = ((const float4*)src)[i];
    unsigned h0, l0, h1, l1;
    split2(v.x, v.y, h0, l0);
    split2(v.z, v.w, h1, l1);
    uint2 hs = make_uint2(h0, h1);
    uint2 ls = make_uint2(l0, l1);
    ((uint2*)hi)[i] = hs;
    ((uint2*)lo)[i] = ls;
}

// ---------------------------------------------------------------------------
// HMMA GEMM, 2-term bf16 split: Y = X @ W^T + bias [+ skip].
// CTA tile 128x128, 8 warps 2(M)x4(N) -> warp 64x32. K-chunks of 64.
// Output either fp32 (Y, with skip) or bf16 hi/lo split (Yh/Yl, with scale).
// ---------------------------------------------------------------------------
#define KC 64
#define NCHUNK (CC / KC)          // 8
#define SROW 144
#define TILE_B (128 * SROW)       // 18432
#define OFF_AH 0
#define OFF_AL TILE_B
#define OFF_BH (2 * TILE_B)
#define OFF_BL (3 * TILE_B)
#define GEMM_SMEM (4 * TILE_B)    // 73728 B

__global__ __launch_bounds__(256, 2) void gemm_mma(
    const __nv_bfloat16* __restrict__ Ah, const __nv_bfloat16* __restrict__ Al,
    const __nv_bfloat16* __restrict__ Bh, const __nv_bfloat16* __restrict__ Bl,
    const float* __restrict__ bias, const float* __restrict__ skip,
    float* __restrict__ Y,
    __nv_bfloat16* __restrict__ Yh, __nv_bfloat16* __restrict__ Yl,
    float scale)
{
    extern __shared__ char smem[];
    const unsigned sb = smem_to_u32(smem);
    const int tid = threadIdx.x;
    const int wid = tid >> 5;
    const int lane = tid & 31;
    const int m0 = blockIdx.y * 128;
    const int n0 = blockIdx.x * 128;
    const int wm = (wid >> 2) * 64;
    const int wn = (wid & 3) * 32;

    float acc[4][4][4];
    #pragma unroll
    for (int i = 0; i < 4; i++)
        #pragma unroll
        for (int j = 0; j < 4; j++)
            #pragma unroll
            for (int r = 0; r < 4; r++) acc[i][j][r] = 0.0f;

    const int a_row = (lane & 15);
    const unsigned a_cb = (unsigned)((lane >> 4) * 16);
    const int b_row = (lane & 7) + ((lane >> 4) << 3);
    const unsigned b_cb = (unsigned)(((lane >> 3) & 1) * 16);

    for (int ck = 0; ck < NCHUNK; ck++) {
        #pragma unroll
        for (int i = tid; i < 1024; i += 256) {
            int r = i >> 3;
            int sg = i & 7;
            unsigned so = (unsigned)(r * SROW + sg * 16);
            size_t ga = (size_t)(m0 + r) * CC + ck * KC + sg * 8;
            size_t gb = (size_t)(n0 + r) * CC + ck * KC + sg * 8;
            *(uint4*)(smem + OFF_AH + so) = *(const uint4*)(Ah + ga);
            *(uint4*)(smem + OFF_AL + so) = *(const uint4*)(Al + ga);
            *(uint4*)(smem + OFF_BH + so) = *(const uint4*)(Bh + gb);
            *(uint4*)(smem + OFF_BL + so) = *(const uint4*)(Bl + gb);
        }
        __syncthreads();

        #pragma unroll
        for (int ks = 0; ks < KC / 16; ks++) {
            const unsigned kb = (unsigned)(ks * 32);
            unsigned b_hi[2][4], b_lo[2][4];
            #pragma unroll
            for (int bj = 0; bj < 2; bj++) {
                unsigned addr = sb + OFF_BH +
                    (unsigned)((wn + bj * 16 + b_row) * SROW) + kb + b_cb;
                LDMATRIX_X4(b_hi[bj], addr);
                LDMATRIX_X4(b_lo[bj], addr + (OFF_BL - OFF_BH));
            }
            #pragma unroll
            for (int mi = 0; mi < 4; mi++) {
                unsigned a_hi[4], a_lo[4];
                unsigned addr = sb + OFF_AH +
                    (unsigned)((wm + mi * 16 + a_row) * SROW) + kb + a_cb;
                LDMATRIX_X4(a_hi, addr);
                LDMATRIX_X4(a_lo, addr + (OFF_AL - OFF_AH));
                #pragma unroll
                for (int nj = 0; nj < 4; nj++) {
                    const unsigned* bh = &b_hi[nj >> 1][(nj & 1) * 2];
                    const unsigned* bl = &b_lo[nj >> 1][(nj & 1) * 2];
                    mma_bf16(acc[mi][nj], a_hi, bh);
                    mma_bf16(acc[mi][nj], a_hi, bl);
                    mma_bf16(acc[mi][nj], a_lo, bh);
                }
            }
        }
        __syncthreads();
    }

    const int g = lane >> 2;
    const int tg = lane & 3;
    #pragma unroll
    for (int mi = 0; mi < 4; mi++) {
        const int mr = m0 + wm + mi * 16 + g;
        #pragma unroll
        for (int nj = 0; nj < 4; nj++) {
            const int n = n0 + wn + nj * 8 + tg * 2;
            float2 bv = *(const float2*)(bias + n);
            float y00 = acc[mi][nj][0] + bv.x;
            float y01 = acc[mi][nj][1] + bv.y;
            float y10 = acc[mi][nj][2] + bv.x;
            float y11 = acc[mi][nj][3] + bv.y;
            if (Yh) {
                y00 *= scale; y01 *= scale; y10 *= scale; y11 *= scale;
                unsigned h0, l0, h1, l1;
                split2(y00, y01, h0, l0);
                split2(y10, y11, h1, l1);
                *(unsigned*)(Yh + (size_t)mr * CC + n) = h0;
                *(unsigned*)(Yl + (size_t)mr * CC + n) = l0;
                *(unsigned*)(Yh + (size_t)(mr + 8) * CC + n) = h1;
                *(unsigned*)(Yl + (size_t)(mr + 8) * CC + n) = l1;
            } else {
                if (skip) {
                    float2 s0 = *(const float2*)(skip + (size_t)mr * CC + n);
                    float2 s1 = *(const float2*)(skip + (size_t)(mr + 8) * CC + n);
                    y00 += s0.x; y01 += s0.y;
                    y10 += s1.x; y11 += s1.y;
                }
                *(float2*)(Y + (size_t)mr * CC + n) = make_float2(y00, y01);
                *(float2*)(Y + (size_t)(mr + 8) * CC + n) = make_float2(y10, y11);
            }
        }
    }
}

// ---------------------------------------------------------------------------
// HMMA flash attention, bf16-split for both matmuls.
// CTA = (b, h, 128-query tile); 8 warps, warp = 16 q-rows x full key chunk.
// Key chunks of 128. Smem: Kh/Kl/Vh/Vl tiles [128][64] bf16, stride 144 B.
// Q (scale pre-folded) staged once through smem into A-fragments.
// ctx written as bf16 hi/lo for the downstream output projection.
// ---------------------------------------------------------------------------
#define AT_SROW 144
#define AT_TILE (128 * AT_SROW)   // 18432
#define AOFF_KH 0
#define AOFF_KL AT_TILE
#define AOFF_VH (2 * AT_TILE)
#define AOFF_VL (3 * AT_TILE)
#define ATTN_SMEM (4 * AT_TILE)   // 73728 B

__global__ __launch_bounds__(256, 1) void attn_mma(
    const __nv_bfloat16* __restrict__ qh, const __nv_bfloat16* __restrict__ ql,
    const __nv_bfloat16* __restrict__ kh, const __nv_bfloat16* __restrict__ kl,
    const __nv_bfloat16* __restrict__ vh, const __nv_bfloat16* __restrict__ vl,
    __nv_bfloat16* __restrict__ oh, __nv_bfloat16* __restrict__ ol)
{
    extern __shared__ char smem[];
    const unsigned sb = smem_to_u32(smem);
    const int tid = threadIdx.x;
    const int wid = tid >> 5;
    const int lane = tid & 31;
    const int g = lane >> 2;
    const int tg = lane & 3;

    const int bh = blockIdx.y;
    const int b = bh >> 3;
    const int h = bh & 7;
    const int q0 = blockIdx.x * 128;
    const size_t base = (size_t)b * SS * CC + (size_t)h * DH;

    // --- Stage Q tile (hi at 0, lo at AT_TILE), build A-fragments ---
    #pragma unroll
    for (int i = tid; i < 1024; i += 256) {
        int r = i >> 3;
        int sg = i & 7;
        unsigned so = (unsigned)(r * AT_SROW + sg * 16);
        size_t ga = base + (size_t)(q0 + r) * CC + sg * 8;
        *(uint4*)(smem + so)           = *(const uint4*)(qh + ga);
        *(uint4*)(smem + AT_TILE + so) = *(const uint4*)(ql + ga);
    }
    __syncthreads();

    const int a_row = (lane & 15);
    const unsigned a_cb = (unsigned)((lane >> 4) * 16);
    unsigned qf_h[4][4], qf_l[4][4];
    #pragma unroll
    for (int ks = 0; ks < 4; ks++) {
        unsigned addr = sb + (unsigned)((wid * 16 + a_row) * AT_SROW) + ks * 32 + a_cb;
        LDMATRIX_X4(qf_h[ks], addr);
        LDMATRIX_X4(qf_l[ks], addr + AT_TILE);
    }
    __syncthreads();

    // ldmatrix lane address components for K (non-trans) and V (trans)
    const int b_row = (lane & 7) + ((lane >> 4) << 3);
    const unsigned b_cb = (unsigned)(((lane >> 3) & 1) * 16);
    const int v_row = (lane & 7) + (((lane >> 3) & 1) << 3);
    const unsigned v_cb = (unsigned)((lane >> 4) * 16);

    float m0r = -1e30f, m1r = -1e30f, l0s = 0.0f, l1s = 0.0f;
    float oacc[8][4];
    #pragma unroll
    for (int t = 0; t < 8; t++)
        #pragma unroll
        for (int r = 0; r < 4; r++) oacc[t][r] = 0.0f;

    for (int kt = 0; kt < SS / 128; kt++) {
        // --- Load K/V hi/lo chunk [128 keys x 64 dh] ---
        #pragma unroll
        for (int i = tid; i < 1024; i += 256) {
            int r = i >> 3;
            int sg = i & 7;
            unsigned so = (unsigned)(r * AT_SROW + sg * 16);
            size_t ga = base + (size_t)(kt * 128 + r) * CC + sg * 8;
            *(uint4*)(smem + AOFF_KH + so) = *(const uint4*)(kh + ga);
            *(uint4*)(smem + AOFF_KL + so) = *(const uint4*)(kl + ga);
            *(uint4*)(smem + AOFF_VH + so) = *(const uint4*)(vh + ga);
            *(uint4*)(smem + AOFF_VL + so) = *(const uint4*)(vl + ga);
        }
        __syncthreads();

        // --- S = Q @ K^T (split) : sacc[nj] covers key cols nj*8.. ---
        float sacc[16][4];
        #pragma unroll
        for (int nj = 0; nj < 16; nj++)
            #pragma unroll
            for (int r = 0; r < 4; r++) sacc[nj][r] = 0.0f;

        #pragma unroll
        for (int ks = 0; ks < 4; ks++) {
            const unsigned kb = (unsigned)(ks * 32);
            #pragma unroll
            for (int nt = 0; nt < 8; nt++) {
                unsigned kb4h[4], kb4l[4];
                unsigned addr = sb + AOFF_KH +
                    (unsigned)((nt * 16 + b_row) * AT_SROW) + kb + b_cb;
                LDMATRIX_X4(kb4h, addr);
                LDMATRIX_X4(kb4l, addr + (AOFF_KL - AOFF_KH));
                mma_bf16(sacc[2 * nt],     qf_h[ks], kb4h);
                mma_bf16(sacc[2 * nt],     qf_h[ks], kb4l);
                mma_bf16(sacc[2 * nt],     qf_l[ks], kb4h);
                mma_bf16(sacc[2 * nt + 1], qf_h[ks], kb4h + 2);
                mma_bf16(sacc[2 * nt + 1], qf_h[ks], kb4l + 2);
                mma_bf16(sacc[2 * nt + 1], qf_l[ks], kb4h + 2);
            }
        }

        // --- Online softmax (rows g and g+8; quad reductions) ---
        float mx0 = -1e30f, mx1 = -1e30f;
        #pragma unroll
        for (int nj = 0; nj < 16; nj++) {
            mx0 = fmaxf(mx0, fmaxf(sacc[nj][0], sacc[nj][1]));
            mx1 = fmaxf(mx1, fmaxf(sacc[nj][2], sacc[nj][3]));
        }
        #pragma unroll
        for (int off = 1; off <= 2; off <<= 1) {
            mx0 = fmaxf(mx0, __shfl_xor_sync(0xffffffffu, mx0, off));
            mx1 = fmaxf(mx1, __shfl_xor_sync(0xffffffffu, mx1, off));
        }
        float nm0 = fmaxf(m0r, mx0);
        float nm1 = fmaxf(m1r, mx1);
        float al0 = __expf(m0r - nm0);
        float al1 = __expf(m1r - nm1);
        m0r = nm0; m1r = nm1;

        float rs0 = 0.0f, rs1 = 0.0f;
        #pragma unroll
        for (int nj = 0; nj < 16; nj++) {
            sacc[nj][0] = __expf(sacc[nj][0] - nm0);
            sacc[nj][1] = __expf(sacc[nj][1] - nm0);
            sacc[nj][2] = __expf(sacc[nj][2] - nm1);
            sacc[nj][3] = __expf(sacc[nj][3] - nm1);
            rs0 += sacc[nj][0] + sacc[nj][1];
            rs1 += sacc[nj][2] + sacc[nj][3];
        }
        #pragma unroll
        for (int off = 1; off <= 2; off <<= 1) {
            rs0 += __shfl_xor_sync(0xffffffffu, rs0, off);
            rs1 += __shfl_xor_sync(0xffffffffu, rs1, off);
        }
        l0s = l0s * al0 + rs0;
        l1s = l1s * al1 + rs1;
        #pragma unroll
        for (int t = 0; t < 8; t++) {
            oacc[t][0] *= al0; oacc[t][1] *= al0;
            oacc[t][2] *= al1; oacc[t][3] *= al1;
        }

        // --- O += P @ V (split). P A-frags straight from sacc registers. ---
        #pragma unroll
        for (int kt2 = 0; kt2 < 8; kt2++) {
            unsigned pa_h[4], pa_l[4];
            split2(sacc[2 * kt2][0],     sacc[2 * kt2][1],     pa_h[0], pa_l[0]);
            split2(sacc[2 * kt2][2],     sacc[2 * kt2][3],     pa_h[1], pa_l[1]);
            split2(sacc[2 * kt2 + 1][0], sacc[2 * kt2 + 1][1], pa_h[2], pa_l[2]);
            split2(sacc[2 * kt2 + 1][2], sacc[2 * kt2 + 1][3], pa_h[3], pa_l[3]);
            #pragma unroll
            for (int dt = 0; dt < 4; dt++) {
                unsigned vb_h[4], vb_l[4];
                unsigned addr = sb + AOFF_VH +
                    (unsigned)((kt2 * 16 + v_row) * AT_SROW) + dt * 32 + v_cb;
                LDMATRIX_X4_TRANS(vb_h, addr);
                LDMATRIX_X4_TRANS(vb_l, addr + (AOFF_VL - AOFF_VH));
                mma_bf16(oacc[2 * dt],     pa_h, vb_h);
                mma_bf16(oacc[2 * dt],     pa_h, vb_l);
                mma_bf16(oacc[2 * dt],     pa_l, vb_h);
                mma_bf16(oacc[2 * dt + 1], pa_h, vb_h + 2);
                mma_bf16(oacc[2 * dt + 1], pa_h, vb_l + 2);
                mma_bf16(oacc[2 * dt + 1], pa_l, vb_h + 2);
            }
        }
        __syncthreads();
    }

    // --- Epilogue: normalize, split to bf16 hi/lo ctx ---
    const float inv0 = 1.0f / l0s;
    const float inv1 = 1.0f / l1s;
    const int r0 = q0 + wid * 16 + g;
    #pragma unroll
    for (int t = 0; t < 8; t++) {
        const int n = t * 8 + tg * 2;
        unsigned h0, lo0, h1, lo1;
        split2(oacc[t][0] * inv0, oacc[t][1] * inv0, h0, lo0);
        split2(oacc[t][2] * inv1, oacc[t][3] * inv1, h1, lo1);
        *(unsigned*)(oh + base + (size_t)r0 * CC + n)       = h0;
        *(unsigned*)(ol + base + (size_t)r0 * CC + n)       = lo0;
        *(unsigned*)(oh + base + (size_t)(r0 + 8) * CC + n) = h1;
        *(unsigned*)(ol + base + (size_t)(r0 + 8) * CC + n) = lo1;
    }
}

// ---------------------------------------------------------------------------
// kernel_launch
// Inputs: x, skip, Wq, bq, Wk, bk, Wv, bv, Wo, bo
// ---------------------------------------------------------------------------
extern "C" void kernel_launch(void* const* d_in, const int* in_sizes, int n_in,
                              void* d_out, int out_size)
{
    const float* x    = (const float*)d_in[0];
    const float* skip = (const float*)d_in[1];
    const float* Wq   = (const float*)d_in[2];
    const float* bq   = (const float*)d_in[3];
    const float* Wk   = (const float*)d_in[4];
    const float* bk   = (const float*)d_in[5];
    const float* Wv   = (const float*)d_in[6];
    const float* bv   = (const float*)d_in[7];
    const float* Wo   = (const float*)d_in[8];
    const float* bo   = (const float*)d_in[9];
    float* out = (float*)d_out;

    __nv_bfloat16 *xh, *xl, *qhp, *qlp, *khp, *klp, *vhp, *vlp, *chp, *clp, *wh, *wl;
    cudaGetSymbolAddress((void**)&xh, g_xh);
    cudaGetSymbolAddress((void**)&xl, g_xl);
    cudaGetSymbolAddress((void**)&qhp, g_qh);
    cudaGetSymbolAddress((void**)&qlp, g_ql);
    cudaGetSymbolAddress((void**)&khp, g_kh);
    cudaGetSymbolAddress((void**)&klp, g_kl);
    cudaGetSymbolAddress((void**)&vhp, g_vh);
    cudaGetSymbolAddress((void**)&vlp, g_vl);
    cudaGetSymbolAddress((void**)&chp, g_ch);
    cudaGetSymbolAddress((void**)&clp, g_cl);
    cudaGetSymbolAddress((void**)&wh, g_wh);
    cudaGetSymbolAddress((void**)&wl, g_wl);

    cudaFuncSetAttribute(gemm_mma,
                         cudaFuncAttributeMaxDynamicSharedMemorySize, GEMM_SMEM);
    cudaFuncSetAttribute(attn_mma,
                         cudaFuncAttributeMaxDynamicSharedMemorySize, ATTN_SMEM);

    // --- splits ---
    const int n4x = MTOT * CC / 4;
    const int n4w = CC * CC / 4;
    split_kernel<<<n4x / 256, 256>>>(x, xh, xl, n4x);
    split_kernel<<<n4w / 256, 256>>>(Wq, wh,               wl,               n4w);
    split_kernel<<<n4w / 256, 256>>>(Wk, wh + CC * CC,     wl + CC * CC,     n4w);
    split_kernel<<<n4w / 256, 256>>>(Wv, wh + 2 * CC * CC, wl + 2 * CC * CC, n4w);
    split_kernel<<<n4w / 256, 256>>>(Wo, wh + 3 * CC * CC, wl + 3 * CC * CC, n4w);

    // --- QKV projections: write bf16 hi/lo directly (Q with 1/8 folded) ---
    dim3 tg(CC / 128, MTOT / 128);     // (4, 64)
    gemm_mma<<<tg, 256, GEMM_SMEM>>>(xh, xl, wh,               wl,               bq, nullptr,
                                     nullptr, qhp, qlp, 0.125f);
    gemm_mma<<<tg, 256, GEMM_SMEM>>>(xh, xl, wh + CC * CC,     wl + CC * CC,     bk, nullptr,
                                     nullptr, khp, klp, 1.0f);
    gemm_mma<<<tg, 256, GEMM_SMEM>>>(xh, xl, wh + 2 * CC * CC, wl + 2 * CC * CC, bv, nullptr,
                                     nullptr, vhp, vlp, 1.0f);

    // --- attention (HMMA, bf16-split) ---
    dim3 agrid(SS / 128, BB * HH);     // (8, 64)
    attn_mma<<<agrid, 256, ATTN_SMEM>>>(qhp, qlp, khp, klp, vhp, vlp, chp, clp);

    // --- output projection + skip (fp32 out) ---
    gemm_mma<<<tg, 256, GEMM_SMEM>>>(chp, clp, wh + 3 * CC * CC, wl + 3 * CC * CC, bo, skip,
                                     out, nullptr, nullptr, 1.0f);
}

// round 17
// speedup vs baseline: 2.9324x; 1.0069x over previous
#include <cuda_runtime.h>
#include <cuda_bf16.h>

// Problem constants
#define BB 8
#define SS 1024
#define CC 512
#define HH 8
#define DH 64
#define MTOT (BB * SS)   // 8192

// ---------------------------------------------------------------------------
// Scratch (no cudaMalloc allowed)
// ---------------------------------------------------------------------------
__device__ __nv_bfloat16 g_xh[MTOT * CC];
__device__ __nv_bfloat16 g_xl[MTOT * CC];
__device__ __nv_bfloat16 g_qh[MTOT * CC];
__device__ __nv_bfloat16 g_ql[MTOT * CC];
__device__ __nv_bfloat16 g_kh[MTOT * CC];
__device__ __nv_bfloat16 g_kl[MTOT * CC];
__device__ __nv_bfloat16 g_vh[MTOT * CC];
__device__ __nv_bfloat16 g_vl[MTOT * CC];
__device__ __nv_bfloat16 g_ch[MTOT * CC];
__device__ __nv_bfloat16 g_cl[MTOT * CC];
__device__ __nv_bfloat16 g_wh[4 * CC * CC];
__device__ __nv_bfloat16 g_wl[4 * CC * CC];

// ---------------------------------------------------------------------------
// PTX helpers (sm_80-era only — ptxas here targets plain sm_103, no tcgen05)
// ---------------------------------------------------------------------------
__device__ __forceinline__ unsigned smem_to_u32(const void* p) {
    unsigned a;
    asm("{ .reg .u64 t; cvta.to.shared.u64 t, %1; cvt.u32.u64 %0, t; }"
        : "=r"(a) : "l"(p));
    return a;
}

__device__ __forceinline__ void cp_async16(unsigned dst, const void* src) {
    asm volatile("cp.async.cg.shared.global [%0], [%1], 16;"
                 :: "r"(dst), "l"(src));
}
#define CP_COMMIT() asm volatile("cp.async.commit_group;" ::: "memory")
#define CP_WAIT1()  asm volatile("cp.async.wait_group 1;" ::: "memory")
#define CP_WAIT0()  asm volatile("cp.async.wait_group 0;" ::: "memory")

#define LDMATRIX_X4(r, addr) \
    asm volatile("ldmatrix.sync.aligned.m8n8.x4.shared.b16 {%0,%1,%2,%3}, [%4];" \
        : "=r"((r)[0]), "=r"((r)[1]), "=r"((r)[2]), "=r"((r)[3]) : "r"(addr))

#define LDMATRIX_X4_TRANS(r, addr) \
    asm volatile("ldmatrix.sync.aligned.m8n8.x4.trans.shared.b16 {%0,%1,%2,%3}, [%4];" \
        : "=r"((r)[0]), "=r"((r)[1]), "=r"((r)[2]), "=r"((r)[3]) : "r"(addr))

__device__ __forceinline__ void mma_bf16(float* d, const unsigned* a, const unsigned* b) {
    asm volatile(
        "mma.sync.aligned.m16n8k16.row.col.f32.bf16.bf16.f32 "
        "{%0,%1,%2,%3}, {%4,%5,%6,%7}, {%8,%9}, {%0,%1,%2,%3};"
        : "+f"(d[0]), "+f"(d[1]), "+f"(d[2]), "+f"(d[3])
        : "r"(a[0]), "r"(a[1]), "r"(a[2]), "r"(a[3]), "r"(b[0]), "r"(b[1]));
}

// Split a float pair into packed bf16x2 hi and lo parts (x -> low element).
__device__ __forceinline__ void split2(float x, float y, unsigned& h, unsigned& l) {
    __nv_bfloat162 hb = __floats2bfloat162_rn(x, y);
    float hx = __bfloat162float(__low2bfloat16(hb));
    float hy = __bfloat162float(__high2bfloat16(hb));
    __nv_bfloat162 lb = __floats2bfloat162_rn(x - hx, y - hy);
    h = *(unsigned*)&hb;
    l = *(unsigned*)&lb;
}

// ---------------------------------------------------------------------------
// fp32 -> (bf16 hi, bf16 lo) split. 4 elements per thread.
// ---------------------------------------------------------------------------
__global__ __launch_bounds__(256) void split_kernel(
    const float* __restrict__ src,
    __nv_bfloat16* __restrict__ hi, __nv_bfloat16* __restrict__ lo, int n4)
{
    int i = blockIdx.x * blockDim.x + threadIdx.x;
    if (i >= n4) return;
    float4 v = ((const float4*)src)[i];
    unsigned h0, l0, h1, l1;
    split2(v.x, v.y, h0, l0);
    split2(v.z, v.w, h1, l1);
    ((uint2*)hi)[i] = make_uint2(h0, h1);
    ((uint2*)lo)[i] = make_uint2(l0, l1);
}

// ---------------------------------------------------------------------------
// Pipelined HMMA GEMM core (2-term bf16 split, cp.async double-buffered).
// CTA tile 128x128, 8 warps 2(M)x4(N). K-chunks of 32, two stages.
// Smem row stride 80 B: rows 8 apart land on disjoint bank quads.
// ---------------------------------------------------------------------------
#define KC 32
#define NCHUNK (CC / KC)      // 16
#define SROW 80
#define TILE_B (128 * SROW)   // 10240
#define STG (4 * TILE_B)      // 40960
#define GEMM_SMEM (2 * STG)   // 81920

__device__ __forceinline__ void gemm_core(
    unsigned sb, int tid, int lane, int wm, int wn,
    const __nv_bfloat16* __restrict__ Ah, const __nv_bfloat16* __restrict__ Al,
    const __nv_bfloat16* __restrict__ Bh, const __nv_bfloat16* __restrict__ Bl,
    int m0, int n0, float acc[4][4][4])
{
    const __nv_bfloat16* ar[4] = {Ah, Al, Bh, Bl};

    auto load_stage = [&](int stg, int ck) {
        #pragma unroll
        for (int j = 0; j < 8; j++) {
            const int arr = j >> 1;             // tid<256 => (tid+256j)>>9 == j>>1
            const int i = tid + j * 256;
            const int r = (i >> 2) & 127;
            const int sg = i & 3;
            unsigned dst = sb + (unsigned)(stg * STG + arr * TILE_B + r * SROW + sg * 16);
            const __nv_bfloat16* src =
                ar[arr] + (size_t)((arr < 2 ? m0 : n0) + r) * CC + ck * KC + sg * 8;
            cp_async16(dst, src);
        }
    };

    const int a_row = (lane & 15);
    const unsigned a_cb = (unsigned)((lane >> 4) * 16);
    const int b_row = (lane & 7) + ((lane >> 4) << 3);
    const unsigned b_cb = (unsigned)(((lane >> 3) & 1) * 16);

    load_stage(0, 0);
    CP_COMMIT();

    for (int ck = 0; ck < NCHUNK; ck++) {
        if (ck + 1 < NCHUNK) {
            load_stage((ck + 1) & 1, ck + 1);
            CP_COMMIT();
            CP_WAIT1();
        } else {
            CP_WAIT0();
        }
        __syncthreads();

        const unsigned so = sb + (unsigned)((ck & 1) * STG);
        #pragma unroll
        for (int ks = 0; ks < 2; ks++) {
            const unsigned kb = (unsigned)(ks * 32);
            unsigned b_hi[2][4], b_lo[2][4];
            #pragma unroll
            for (int bj = 0; bj < 2; bj++) {
                unsigned addr = so + 2 * TILE_B +
                    (unsigned)((wn + bj * 16 + b_row) * SROW) + kb + b_cb;
                LDMATRIX_X4(b_hi[bj], addr);
                LDMATRIX_X4(b_lo[bj], addr + TILE_B);
            }
            #pragma unroll
            for (int mi = 0; mi < 4; mi++) {
                unsigned a_hi[4], a_lo[4];
                unsigned addr = so +
                    (unsigned)((wm + mi * 16 + a_row) * SROW) + kb + a_cb;
                LDMATRIX_X4(a_hi, addr);
                LDMATRIX_X4(a_lo, addr + TILE_B);
                #pragma unroll
                for (int nj = 0; nj < 4; nj++) {
                    const unsigned* bh = &b_hi[nj >> 1][(nj & 1) * 2];
                    const unsigned* bl = &b_lo[nj >> 1][(nj & 1) * 2];
                    mma_bf16(acc[mi][nj], a_hi, bh);
                    mma_bf16(acc[mi][nj], a_hi, bl);
                    mma_bf16(acc[mi][nj], a_lo, bh);
                }
            }
        }
        __syncthreads();
    }
}

// ---------------------------------------------------------------------------
// Merged QKV projection: grid (12, 64); blockIdx.x selects weight (0..2) and
// n-block (0..3). Writes bf16 hi/lo (Q with 1/8 scale folded).
// ---------------------------------------------------------------------------
__global__ __launch_bounds__(256, 2) void gemm_qkv(
    const __nv_bfloat16* __restrict__ xh, const __nv_bfloat16* __restrict__ xl,
    const __nv_bfloat16* __restrict__ w_h, const __nv_bfloat16* __restrict__ w_l,
    const float* __restrict__ bq, const float* __restrict__ bk,
    const float* __restrict__ bv,
    __nv_bfloat16* __restrict__ qh, __nv_bfloat16* __restrict__ ql,
    __nv_bfloat16* __restrict__ kh, __nv_bfloat16* __restrict__ kl,
    __nv_bfloat16* __restrict__ vh, __nv_bfloat16* __restrict__ vl)
{
    extern __shared__ char smem[];
    const unsigned sb = smem_to_u32(smem);
    const int tid = threadIdx.x;
    const int wid = tid >> 5;
    const int lane = tid & 31;
    const int wsel = blockIdx.x >> 2;
    const int n0 = (blockIdx.x & 3) * 128;
    const int m0 = blockIdx.y * 128;
    const int wm = (wid >> 2) * 64;
    const int wn = (wid & 3) * 32;

    const __nv_bfloat16* Bh = w_h + (size_t)wsel * CC * CC;
    const __nv_bfloat16* Bl = w_l + (size_t)wsel * CC * CC;
    const float* bias = (wsel == 0) ? bq : ((wsel == 1) ? bk : bv);
    __nv_bfloat16* Yh = (wsel == 0) ? qh : ((wsel == 1) ? kh : vh);
    __nv_bfloat16* Yl = (wsel == 0) ? ql : ((wsel == 1) ? kl : vl);
    const float scale = (wsel == 0) ? 0.125f : 1.0f;

    float acc[4][4][4];
    #pragma unroll
    for (int i = 0; i < 4; i++)
        #pragma unroll
        for (int j = 0; j < 4; j++)
            #pragma unroll
            for (int r = 0; r < 4; r++) acc[i][j][r] = 0.0f;

    gemm_core(sb, tid, lane, wm, wn, xh, xl, Bh, Bl, m0, n0, acc);

    const int g = lane >> 2;
    const int tg = lane & 3;
    #pragma unroll
    for (int mi = 0; mi < 4; mi++) {
        const int mr = m0 + wm + mi * 16 + g;
        #pragma unroll
        for (int nj = 0; nj < 4; nj++) {
            const int n = n0 + wn + nj * 8 + tg * 2;
            float2 bv2 = *(const float2*)(bias + n);
            float y00 = (acc[mi][nj][0] + bv2.x) * scale;
            float y01 = (acc[mi][nj][1] + bv2.y) * scale;
            float y10 = (acc[mi][nj][2] + bv2.x) * scale;
            float y11 = (acc[mi][nj][3] + bv2.y) * scale;
            unsigned h0, l0, h1, l1;
            split2(y00, y01, h0, l0);
            split2(y10, y11, h1, l1);
            *(unsigned*)(Yh + (size_t)mr * CC + n)       = h0;
            *(unsigned*)(Yl + (size_t)mr * CC + n)       = l0;
            *(unsigned*)(Yh + (size_t)(mr + 8) * CC + n) = h1;
            *(unsigned*)(Yl + (size_t)(mr + 8) * CC + n) = l1;
        }
    }
}

// ---------------------------------------------------------------------------
// Output projection: fp32 out + bias + skip.
// ---------------------------------------------------------------------------
__global__ __launch_bounds__(256, 2) void gemm_out(
    const __nv_bfloat16* __restrict__ Ah, const __nv_bfloat16* __restrict__ Al,
    const __nv_bfloat16* __restrict__ Bh, const __nv_bfloat16* __restrict__ Bl,
    const float* __restrict__ bias, const float* __restrict__ skip,
    float* __restrict__ Y)
{
    extern __shared__ char smem[];
    const unsigned sb = smem_to_u32(smem);
    const int tid = threadIdx.x;
    const int wid = tid >> 5;
    const int lane = tid & 31;
    const int m0 = blockIdx.y * 128;
    const int n0 = blockIdx.x * 128;
    const int wm = (wid >> 2) * 64;
    const int wn = (wid & 3) * 32;

    float acc[4][4][4];
    #pragma unroll
    for (int i = 0; i < 4; i++)
        #pragma unroll
        for (int j = 0; j < 4; j++)
            #pragma unroll
            for (int r = 0; r < 4; r++) acc[i][j][r] = 0.0f;

    gemm_core(sb, tid, lane, wm, wn, Ah, Al, Bh, Bl, m0, n0, acc);

    const int g = lane >> 2;
    const int tg = lane & 3;
    #pragma unroll
    for (int mi = 0; mi < 4; mi++) {
        const int mr = m0 + wm + mi * 16 + g;
        #pragma unroll
        for (int nj = 0; nj < 4; nj++) {
            const int n = n0 + wn + nj * 8 + tg * 2;
            float2 bv2 = *(const float2*)(bias + n);
            float2 s0 = *(const float2*)(skip + (size_t)mr * CC + n);
            float2 s1 = *(const float2*)(skip + (size_t)(mr + 8) * CC + n);
            *(float2*)(Y + (size_t)mr * CC + n) =
                make_float2(acc[mi][nj][0] + bv2.x + s0.x,
                            acc[mi][nj][1] + bv2.y + s0.y);
            *(float2*)(Y + (size_t)(mr + 8) * CC + n) =
                make_float2(acc[mi][nj][2] + bv2.x + s1.x,
                            acc[mi][nj][3] + bv2.y + s1.y);
        }
    }
}

// ---------------------------------------------------------------------------
// HMMA flash attention, bf16-split, cp.async double-buffered K/V chunks.
// CTA = (b, h, 128-query tile); 8 warps x 16 q-rows. Key chunks of 128.
// ---------------------------------------------------------------------------
#define AT_SROW 144
#define AT_TILE (128 * AT_SROW)   // 18432
#define ASTG (4 * AT_TILE)        // 73728
#define ATTN_SMEM (2 * ASTG)      // 147456

__global__ __launch_bounds__(256, 1) void attn_mma(
    const __nv_bfloat16* __restrict__ qh, const __nv_bfloat16* __restrict__ ql,
    const __nv_bfloat16* __restrict__ kh, const __nv_bfloat16* __restrict__ kl,
    const __nv_bfloat16* __restrict__ vh, const __nv_bfloat16* __restrict__ vl,
    __nv_bfloat16* __restrict__ oh, __nv_bfloat16* __restrict__ ol)
{
    extern __shared__ char smem[];
    const unsigned sb = smem_to_u32(smem);
    const int tid = threadIdx.x;
    const int wid = tid >> 5;
    const int lane = tid & 31;
    const int g = lane >> 2;
    const int tg = lane & 3;

    const int bh = blockIdx.y;
    const int b = bh >> 3;
    const int h = bh & 7;
    const int q0 = blockIdx.x * 128;
    const size_t base = (size_t)b * SS * CC + (size_t)h * DH;

    // --- Stage Q tile (hi at 0, lo at AT_TILE), build A-fragments ---
    #pragma unroll
    for (int i = tid; i < 1024; i += 256) {
        int r = i >> 3;
        int sg = i & 7;
        unsigned so = (unsigned)(r * AT_SROW + sg * 16);
        size_t ga = base + (size_t)(q0 + r) * CC + sg * 8;
        *(uint4*)(smem + so)           = *(const uint4*)(qh + ga);
        *(uint4*)(smem + AT_TILE + so) = *(const uint4*)(ql + ga);
    }
    __syncthreads();

    const int a_row = (lane & 15);
    const unsigned a_cb = (unsigned)((lane >> 4) * 16);
    unsigned qf_h[4][4], qf_l[4][4];
    #pragma unroll
    for (int ks = 0; ks < 4; ks++) {
        unsigned addr = sb + (unsigned)((wid * 16 + a_row) * AT_SROW) + ks * 32 + a_cb;
        LDMATRIX_X4(qf_h[ks], addr);
        LDMATRIX_X4(qf_l[ks], addr + AT_TILE);
    }
    __syncthreads();

    const __nv_bfloat16* kv[4] = {kh, kl, vh, vl};
    auto load_kv = [&](int stg, int kt) {
        #pragma unroll
        for (int j = 0; j < 16; j++) {
            const int arr = j >> 2;             // tid<256 => (tid+256j)>>10 == j>>2
            const int i = tid + j * 256;
            const int r = (i >> 3) & 127;
            const int sg = i & 7;
            unsigned dst = sb + (unsigned)(stg * ASTG + arr * AT_TILE + r * AT_SROW + sg * 16);
            const __nv_bfloat16* src = kv[arr] + base + (size_t)(kt * 128 + r) * CC + sg * 8;
            cp_async16(dst, src);
        }
    };

    const int b_row = (lane & 7) + ((lane >> 4) << 3);
    const unsigned b_cb = (unsigned)(((lane >> 3) & 1) * 16);
    const int v_row = (lane & 7) + (((lane >> 3) & 1) << 3);
    const unsigned v_cb = (unsigned)((lane >> 4) * 16);

    float m0r = -1e30f, m1r = -1e30f, l0s = 0.0f, l1s = 0.0f;
    float oacc[8][4];
    #pragma unroll
    for (int t = 0; t < 8; t++)
        #pragma unroll
        for (int r = 0; r < 4; r++) oacc[t][r] = 0.0f;

    load_kv(0, 0);
    CP_COMMIT();

    for (int kt = 0; kt < SS / 128; kt++) {
        if (kt + 1 < SS / 128) {
            load_kv((kt + 1) & 1, kt + 1);
            CP_COMMIT();
            CP_WAIT1();
        } else {
            CP_WAIT0();
        }
        __syncthreads();
        const unsigned so = sb + (unsigned)((kt & 1) * ASTG);

        // --- S = Q @ K^T (split) ---
        float sacc[16][4];
        #pragma unroll
        for (int nj = 0; nj < 16; nj++)
            #pragma unroll
            for (int r = 0; r < 4; r++) sacc[nj][r] = 0.0f;

        #pragma unroll
        for (int ks = 0; ks < 4; ks++) {
            const unsigned kb = (unsigned)(ks * 32);
            #pragma unroll
            for (int nt = 0; nt < 8; nt++) {
                unsigned kb4h[4], kb4l[4];
                unsigned addr = so + (unsigned)((nt * 16 + b_row) * AT_SROW) + kb + b_cb;
                LDMATRIX_X4(kb4h, addr);
                LDMATRIX_X4(kb4l, addr + AT_TILE);
                mma_bf16(sacc[2 * nt],     qf_h[ks], kb4h);
                mma_bf16(sacc[2 * nt],     qf_h[ks], kb4l);
                mma_bf16(sacc[2 * nt],     qf_l[ks], kb4h);
                mma_bf16(sacc[2 * nt + 1], qf_h[ks], kb4h + 2);
                mma_bf16(sacc[2 * nt + 1], qf_h[ks], kb4l + 2);
                mma_bf16(sacc[2 * nt + 1], qf_l[ks], kb4h + 2);
            }
        }

        // --- Online softmax (rows g and g+8; quad reductions) ---
        float mx0 = -1e30f, mx1 = -1e30f;
        #pragma unroll
        for (int nj = 0; nj < 16; nj++) {
            mx0 = fmaxf(mx0, fmaxf(sacc[nj][0], sacc[nj][1]));
            mx1 = fmaxf(mx1, fmaxf(sacc[nj][2], sacc[nj][3]));
        }
        #pragma unroll
        for (int off = 1; off <= 2; off <<= 1) {
            mx0 = fmaxf(mx0, __shfl_xor_sync(0xffffffffu, mx0, off));
            mx1 = fmaxf(mx1, __shfl_xor_sync(0xffffffffu, mx1, off));
        }
        float nm0 = fmaxf(m0r, mx0);
        float nm1 = fmaxf(m1r, mx1);
        float al0 = __expf(m0r - nm0);
        float al1 = __expf(m1r - nm1);
        m0r = nm0; m1r = nm1;

        float rs0 = 0.0f, rs1 = 0.0f;
        #pragma unroll
        for (int nj = 0; nj < 16; nj++) {
            sacc[nj][0] = __expf(sacc[nj][0] - nm0);
            sacc[nj][1] = __expf(sacc[nj][1] - nm0);
            sacc[nj][2] = __expf(sacc[nj][2] - nm1);
            sacc[nj][3] = __expf(sacc[nj][3] - nm1);
            rs0 += sacc[nj][0] + sacc[nj][1];
            rs1 += sacc[nj][2] + sacc[nj][3];
        }
        #pragma unroll
        for (int off = 1; off <= 2; off <<= 1) {
            rs0 += __shfl_xor_sync(0xffffffffu, rs0, off);
            rs1 += __shfl_xor_sync(0xffffffffu, rs1, off);
        }
        l0s = l0s * al0 + rs0;
        l1s = l1s * al1 + rs1;
        #pragma unroll
        for (int t = 0; t < 8; t++) {
            oacc[t][0] *= al0; oacc[t][1] *= al0;
            oacc[t][2] *= al1; oacc[t][3] *= al1;
        }

        // --- O += P @ V (split) ---
        #pragma unroll
        for (int kt2 = 0; kt2 < 8; kt2++) {
            unsigned pa_h[4], pa_l[4];
            split2(sacc[2 * kt2][0],     sacc[2 * kt2][1],     pa_h[0], pa_l[0]);
            split2(sacc[2 * kt2][2],     sacc[2 * kt2][3],     pa_h[1], pa_l[1]);
            split2(sacc[2 * kt2 + 1][0], sacc[2 * kt2 + 1][1], pa_h[2], pa_l[2]);
            split2(sacc[2 * kt2 + 1][2], sacc[2 * kt2 + 1][3], pa_h[3], pa_l[3]);
            #pragma unroll
            for (int dt = 0; dt < 4; dt++) {
                unsigned vb_h[4], vb_l[4];
                unsigned addr = so + 2 * AT_TILE +
                    (unsigned)((kt2 * 16 + v_row) * AT_SROW) + dt * 32 + v_cb;
                LDMATRIX_X4_TRANS(vb_h, addr);
                LDMATRIX_X4_TRANS(vb_l, addr + AT_TILE);
                mma_bf16(oacc[2 * dt],     pa_h, vb_h);
                mma_bf16(oacc[2 * dt],     pa_h, vb_l);
                mma_bf16(oacc[2 * dt],     pa_l, vb_h);
                mma_bf16(oacc[2 * dt + 1], pa_h, vb_h + 2);
                mma_bf16(oacc[2 * dt + 1], pa_h, vb_l + 2);
                mma_bf16(oacc[2 * dt + 1], pa_l, vb_h + 2);
            }
        }
        __syncthreads();
    }

    // --- Epilogue: normalize, split to bf16 hi/lo ctx ---
    const float inv0 = 1.0f / l0s;
    const float inv1 = 1.0f / l1s;
    const int r0 = q0 + wid * 16 + g;
    #pragma unroll
    for (int t = 0; t < 8; t++) {
        const int n = t * 8 + tg * 2;
        unsigned h0, lo0, h1, lo1;
        split2(oacc[t][0] * inv0, oacc[t][1] * inv0, h0, lo0);
        split2(oacc[t][2] * inv1, oacc[t][3] * inv1, h1, lo1);
        *(unsigned*)(oh + base + (size_t)r0 * CC + n)       = h0;
        *(unsigned*)(ol + base + (size_t)r0 * CC + n)       = lo0;
        *(unsigned*)(oh + base + (size_t)(r0 + 8) * CC + n) = h1;
        *(unsigned*)(ol + base + (size_t)(r0 + 8) * CC + n) = lo1;
    }
}

// ---------------------------------------------------------------------------
// kernel_launch
// Inputs: x, skip, Wq, bq, Wk, bk, Wv, bv, Wo, bo
// ---------------------------------------------------------------------------
extern "C" void kernel_launch(void* const* d_in, const int* in_sizes, int n_in,
                              void* d_out, int out_size)
{
    const float* x    = (const float*)d_in[0];
    const float* skip = (const float*)d_in[1];
    const float* Wq   = (const float*)d_in[2];
    const float* bq   = (const float*)d_in[3];
    const float* Wk   = (const float*)d_in[4];
    const float* bk   = (const float*)d_in[5];
    const float* Wv   = (const float*)d_in[6];
    const float* bv   = (const float*)d_in[7];
    const float* Wo   = (const float*)d_in[8];
    const float* bo   = (const float*)d_in[9];
    float* out = (float*)d_out;

    __nv_bfloat16 *xh, *xl, *qhp, *qlp, *khp, *klp, *vhp, *vlp, *chp, *clp, *wh, *wl;
    cudaGetSymbolAddress((void**)&xh, g_xh);
    cudaGetSymbolAddress((void**)&xl, g_xl);
    cudaGetSymbolAddress((void**)&qhp, g_qh);
    cudaGetSymbolAddress((void**)&qlp, g_ql);
    cudaGetSymbolAddress((void**)&khp, g_kh);
    cudaGetSymbolAddress((void**)&klp, g_kl);
    cudaGetSymbolAddress((void**)&vhp, g_vh);
    cudaGetSymbolAddress((void**)&vlp, g_vl);
    cudaGetSymbolAddress((void**)&chp, g_ch);
    cudaGetSymbolAddress((void**)&clp, g_cl);
    cudaGetSymbolAddress((void**)&wh, g_wh);
    cudaGetSymbolAddress((void**)&wl, g_wl);

    cudaFuncSetAttribute(gemm_qkv,
                         cudaFuncAttributeMaxDynamicSharedMemorySize, GEMM_SMEM);
    cudaFuncSetAttribute(gemm_out,
                         cudaFuncAttributeMaxDynamicSharedMemorySize, GEMM_SMEM);
    cudaFuncSetAttribute(attn_mma,
                         cudaFuncAttributeMaxDynamicSharedMemorySize, ATTN_SMEM);

    // --- splits ---
    const int n4x = MTOT * CC / 4;
    const int n4w = CC * CC / 4;
    split_kernel<<<n4x / 256, 256>>>(x, xh, xl, n4x);
    split_kernel<<<n4w / 256, 256>>>(Wq, wh,               wl,               n4w);
    split_kernel<<<n4w / 256, 256>>>(Wk, wh + CC * CC,     wl + CC * CC,     n4w);
    split_kernel<<<n4w / 256, 256>>>(Wv, wh + 2 * CC * CC, wl + 2 * CC * CC, n4w);
    split_kernel<<<n4w / 256, 256>>>(Wo, wh + 3 * CC * CC, wl + 3 * CC * CC, n4w);

    // --- merged QKV projection (one launch, 768 CTAs) ---
    dim3 qkvg(12, MTOT / 128);         // (12, 64)
    gemm_qkv<<<qkvg, 256, GEMM_SMEM>>>(xh, xl, wh, wl, bq, bk, bv,
                                       qhp, qlp, khp, klp, vhp, vlp);

    // --- attention (HMMA, bf16-split, pipelined) ---
    dim3 agrid(SS / 128, BB * HH);     // (8, 64)
    attn_mma<<<agrid, 256, ATTN_SMEM>>>(qhp, qlp, khp, klp, vhp, vlp, chp, clp);

    // --- output projection + skip (fp32 out, pipelined) ---
    dim3 og(CC / 128, MTOT / 128);     // (4, 64)
    gemm_out<<<og, 256, GEMM_SMEM>>>(chp, clp, wh + 3 * CC * CC, wl + 3 * CC * CC,
                                     bo, skip, out);
}